// round 15
// baseline (speedup 1.0000x reference)
#include <cuda_runtime.h>
#include <cuda_fp16.h>
#include <cstdint>
#include <cstddef>

// ---------------- problem constants ----------------
static constexpr int T_TOK = 16384;
static constexpr int DDIM  = 2880;
static constexpr int HDIM  = 2880;
static constexpr int NEXP  = 8;
static constexpr int CEXP  = T_TOK / NEXP;   // 2048 tokens per expert
static constexpr int N1    = 2 * HDIM;       // 5760
static constexpr int KDIM  = 2880;

// ---------------- tile config (2 CTAs / SM) ----------------
static constexpr int BM = 128;
static constexpr int BN = 160;               // 5760/160=36, 2880/160=18 (both exact)
static constexpr int BK = 64;                // 128 bytes of fp16 per row-slice
static constexpr int KI = KDIM / BK;         // 45
static constexpr int NSTAGE = 3;
static constexpr int NTHREADS = 128;         // 4 warps: 2(m) x 2(n)

static constexpr int WM = 64;                // warp tile M
static constexpr int WN = 80;                // warp tile N

static constexpr int A_STAGE = BM * 128;     // 16384 B
static constexpr int B_STAGE = BN * 128;     // 20480 B
static constexpr int A_OFF    = 0;
static constexpr int B_OFF    = NSTAGE * A_STAGE;             // 49152
static constexpr int BIAS_OFF = B_OFF + NSTAGE * B_STAGE;     // 110592
static constexpr int SMEM_USE  = BIAS_OFF + BN * 4;           // 111232
static constexpr int SMEM_BYTES = SMEM_USE + 256;             // 111488 (x2 = 222.9K/SM)

// ---- fused W2-conversion tail blocks (ride along with GEMM1's launch) ----
// unit = 2 float4 (32B fp32) -> 1 uint4 (16B fp16)
static constexpr long long NW2_U      = (long long)NEXP * DDIM * HDIM / 8;  // 8,294,400 units
static constexpr int       CVT_CHUNK_U = 2048;                              // units per cvt block
static constexpr int       NCVT_BLK   = (int)(NW2_U / CVT_CHUNK_U);         // 4050 (exact)
static constexpr int       G1X = N1 / BN;      // 36
static constexpr int       G1Y = CEXP / BM;    // 16
static constexpr int       ZEXTRA = (NCVT_BLK + G1X * G1Y - 1) / (G1X * G1Y); // 8

// ---------------- scratch (static device arrays: no allocation) -----------
__device__ __half g_Xh [(size_t)T_TOK * DDIM];
__device__ __half g_W1h[(size_t)NEXP * N1 * KDIM];
__device__ __half g_W2h[(size_t)NEXP * DDIM * HDIM];
__device__ __half g_Sh [(size_t)T_TOK * HDIM];

// ---------------- PTX helpers ----------------
__device__ __forceinline__ uint32_t smem_u32(const void* p) {
    uint32_t a;
    asm("{ .reg .u64 t; cvta.to.shared.u64 t, %1; cvt.u32.u64 %0, t; }"
        : "=r"(a) : "l"(p));
    return a;
}

__device__ __forceinline__ uint32_t swz128(uint32_t off) {
    return off ^ ((off >> 3) & 0x70);
}

__device__ __forceinline__ void cp16(uint32_t dst, const void* src) {
    asm volatile("cp.async.cg.shared.global [%0], [%1], 16;"
                 :: "r"(dst), "l"(src) : "memory");
}
__device__ __forceinline__ void cp_commit() {
    asm volatile("cp.async.commit_group;" ::: "memory");
}
__device__ __forceinline__ void cp_wait1() {
    asm volatile("cp.async.wait_group 1;" ::: "memory");
}

__device__ __forceinline__ void ldsm_x4(uint32_t* d, uint32_t addr) {
    asm volatile("ldmatrix.sync.aligned.m8n8.x4.shared.b16 {%0,%1,%2,%3}, [%4];"
                 : "=r"(d[0]), "=r"(d[1]), "=r"(d[2]), "=r"(d[3]) : "r"(addr));
}

__device__ __forceinline__ void mma16816(float* c, const uint32_t* a,
                                         uint32_t b0, uint32_t b1) {
    asm volatile("mma.sync.aligned.m16n8k16.row.col.f32.f16.f16.f32 "
                 "{%0,%1,%2,%3}, {%4,%5,%6,%7}, {%8,%9}, {%0,%1,%2,%3};"
                 : "+f"(c[0]), "+f"(c[1]), "+f"(c[2]), "+f"(c[3])
                 : "r"(a[0]), "r"(a[1]), "r"(a[2]), "r"(a[3]),
                   "r"(b0), "r"(b1));
}

// 2x float4 -> uint4 (8 fp32 -> 8 fp16), streaming loads
__device__ __forceinline__ uint4 cvt8(const float4* __restrict__ p) {
    float4 a = __ldcs(p);
    float4 b = __ldcs(p + 1);
    __half2 h0 = __floats2half2_rn(a.x, a.y);
    __half2 h1 = __floats2half2_rn(a.z, a.w);
    __half2 h2 = __floats2half2_rn(b.x, b.y);
    __half2 h3 = __floats2half2_rn(b.z, b.w);
    uint4 o;
    o.x = *reinterpret_cast<const uint32_t*>(&h0);
    o.y = *reinterpret_cast<const uint32_t*>(&h1);
    o.z = *reinterpret_cast<const uint32_t*>(&h2);
    o.w = *reinterpret_cast<const uint32_t*>(&h3);
    return o;
}

// ---------------- fp32 -> fp16 convert: X and W1 in one launch ----------------
// unit i: converts elements [8i, 8i+8). X units first, then W1 units.
__global__ void cvt_xw1(const float4* __restrict__ xs, uint4* __restrict__ xd,
                        long long nxu,
                        const float4* __restrict__ ws, uint4* __restrict__ wd,
                        long long ntotu) {
    const long long stride = (long long)gridDim.x * blockDim.x;
    long long i = (long long)blockIdx.x * blockDim.x + threadIdx.x;
    #pragma unroll
    for (int r = 0; r < 2; ++r, i += stride) {
        if (i < nxu) {
            __stcs(xd + i, cvt8(xs + 2 * i));
        } else if (i < ntotu) {
            long long j = i - nxu;
            __stcs(wd + j, cvt8(ws + 2 * j));
        }
    }
}

// ---------------- fused GEMM (+swiglu on EPI==0) ----------------
// D[m, n] = sum_k A[m, k] * B[n, k]  (both K-major fp16)
// EPI==0: out = __half S after swiglu on (even, odd) col pairs; grid.z > NEXP
//         blocks are W2 fp32->fp16 convert blocks (tail-filled behind GEMM)
// EPI==1: out = float + bias
template <int EPI>
__global__ void __launch_bounds__(NTHREADS, 2)
gemm_f16(const __half* __restrict__ A,
         const __half* __restrict__ B,
         const float* __restrict__ bias,
         void* __restrict__ outp,
         int Ntot,
         const float4* __restrict__ cvt_src,
         uint4* __restrict__ cvt_dst) {
    const int tid = threadIdx.x;

    if (EPI == 0 && blockIdx.z >= (unsigned)NEXP) {
        // -------- W2 conversion tail block --------
        int cid = (int)blockIdx.x +
                  (int)gridDim.x * ((int)blockIdx.y +
                  (int)gridDim.y * ((int)blockIdx.z - NEXP));
        if (cid < NCVT_BLK) {
            long long base = (long long)cid * CVT_CHUNK_U + tid;
            #pragma unroll
            for (int j = 0; j < CVT_CHUNK_U / NTHREADS; ++j) {
                long long idx = base + (long long)j * NTHREADS;
                __stcs(cvt_dst + idx, cvt8(cvt_src + 2 * idx));
            }
        }
        return;
    }

    extern __shared__ char smem_raw[];
    const uint32_t sbase = smem_u32(smem_raw);

    const int lane = tid & 31;
    const int wid  = tid >> 5;               // 0..3
    const int wm   = (wid & 1) * WM;         // warp M offset (2 warps in M)
    const int wn   = (wid >> 1) * WN;        // warp N offset (2 warps in N)

    const int bn  = blockIdx.x;
    const int bm  = blockIdx.y;
    const int e   = blockIdx.z;
    const int n0  = bn * BN;
    const size_t row0 = (size_t)e * CEXP + (size_t)bm * BM;

    const __half* Aexp = A + row0 * KDIM;
    const __half* Bexp = B + ((size_t)e * Ntot + n0) * KDIM;

    // bias tile -> smem
    for (int i = tid; i < BN; i += NTHREADS) {
        float v = bias[(size_t)e * Ntot + n0 + i];
        asm volatile("st.shared.f32 [%0], %1;"
                     :: "r"(sbase + BIAS_OFF + i * 4), "f"(v) : "memory");
    }

    // ---- stage loader (A: 1024 chunks -> 8/thread, B: 1280 -> 10/thread) ----
    auto load_stage = [&](int s_, int kt) {
        const int koff = kt * BK;
        const uint32_t abase = sbase + A_OFF + s_ * A_STAGE;
        const uint32_t bbase = sbase + B_OFF + s_ * B_STAGE;
        #pragma unroll
        for (int j = 0; j < 8; ++j) {
            int c = tid + j * NTHREADS;
            int r = c >> 3, q = c & 7;
            cp16(abase + swz128((uint32_t)(r * 128 + q * 16)),
                 Aexp + (size_t)r * KDIM + koff + q * 8);
        }
        #pragma unroll
        for (int j = 0; j < 10; ++j) {
            int c = tid + j * NTHREADS;
            int r = c >> 3, q = c & 7;
            cp16(bbase + swz128((uint32_t)(r * 128 + q * 16)),
                 Bexp + (size_t)r * KDIM + koff + q * 8);
        }
    };

    // prologue: fill stages 0,1 (one commit group each)
    load_stage(0, 0); cp_commit();
    load_stage(1, 1); cp_commit();

    // accumulators: 4 m-frags x 10 n8-frags x 4 floats = 160 regs
    float acc[4][10][4];
    #pragma unroll
    for (int i = 0; i < 4; ++i)
        #pragma unroll
        for (int j = 0; j < 10; ++j)
            #pragma unroll
            for (int q = 0; q < 4; ++q) acc[i][j][q] = 0.0f;

    // per-lane ldmatrix row/col selectors (stage-invariant parts)
    const int a_row  = wm + (lane & 15);        // + mf*16
    const int a_k8   = (lane >> 4) * 16;        // byte offset within 32B k-step
    const int b_row  = wn + ((lane & 15) & 7) + 8 * (lane >> 4);  // + nf*16
    const int b_k8   = (((lane & 15) >> 3)) * 16;

    int s  = 0;       // compute stage
    int sj = 2;       // load stage
    for (int it = 0; it < KI; ++it) {
        // one commit group per iteration (possibly empty) keeps wait_group exact
        cp_wait1();
        __syncthreads();

        const int jn = it + 2;
        if (jn < KI) load_stage(sj, jn);
        cp_commit();

        const uint32_t sA = sbase + A_OFF + s * A_STAGE;
        const uint32_t sB = sbase + B_OFF + s * B_STAGE;

        #pragma unroll
        for (int ks = 0; ks < 4; ++ks) {
            const int kb = ks * 32;
            uint32_t a[4][4];
            #pragma unroll
            for (int mf = 0; mf < 4; ++mf)
                ldsm_x4(a[mf], sA + swz128((uint32_t)((a_row + mf * 16) * 128 + kb + a_k8)));
            #pragma unroll
            for (int nf = 0; nf < 5; ++nf) {
                uint32_t b[4];
                ldsm_x4(b, sB + swz128((uint32_t)((b_row + nf * 16) * 128 + kb + b_k8)));
                #pragma unroll
                for (int mf = 0; mf < 4; ++mf) {
                    mma16816(acc[mf][2 * nf],     a[mf], b[0], b[1]);
                    mma16816(acc[mf][2 * nf + 1], a[mf], b[2], b[3]);
                }
            }
        }
        s  = (s  == NSTAGE - 1) ? 0 : s + 1;
        sj = (sj == NSTAGE - 1) ? 0 : sj + 1;
    }
    __syncthreads();

    // ---------------- epilogue ----------------
    const int grp = lane >> 2;        // row within m16 frag
    const int tq  = lane & 3;         // col pair selector

    #pragma unroll
    for (int mf = 0; mf < 4; ++mf) {
        const size_t r0g = row0 + wm + mf * 16 + grp;
        const size_t r1g = r0g + 8;
        #pragma unroll
        for (int nf = 0; nf < 10; ++nf) {
            const int ncol = wn + nf * 8 + 2 * tq;     // even col in tile
            float bg, bl;
            asm volatile("ld.shared.f32 %0, [%1];" : "=f"(bg)
                         : "r"(sbase + BIAS_OFF + ncol * 4));
            asm volatile("ld.shared.f32 %0, [%1];" : "=f"(bl)
                         : "r"(sbase + BIAS_OFF + (ncol + 1) * 4));
            if (EPI == 0) {
                // swiglu: g = even col, l = odd col
                #pragma unroll
                for (int half_ : {0, 1}) {
                    float g = acc[mf][nf][2 * half_]     + bg;
                    float l = acc[mf][nf][2 * half_ + 1] + bl;
                    g = fminf(g, 7.0f);
                    l = fminf(fmaxf(l, -7.0f), 7.0f);
                    float sig = 1.0f / (1.0f + __expf(-1.702f * g));
                    float sv  = g * sig * (l + 1.0f);
                    size_t row = half_ ? r1g : r0g;
                    ((__half*)outp)[row * (size_t)HDIM + ((n0 + ncol) >> 1)] = __float2half_rn(sv);
                }
            } else {
                float2 v0 = make_float2(acc[mf][nf][0] + bg, acc[mf][nf][1] + bl);
                float2 v1 = make_float2(acc[mf][nf][2] + bg, acc[mf][nf][3] + bl);
                float* oo = (float*)outp;
                *reinterpret_cast<float2*>(oo + r0g * (size_t)DDIM + n0 + ncol) = v0;
                *reinterpret_cast<float2*>(oo + r1g * (size_t)DDIM + n0 + ncol) = v1;
            }
        }
    }
}

// ---------------- launch ----------------
extern "C" void kernel_launch(void* const* d_in, const int* in_sizes, int n_in,
                              void* d_out, int out_size) {
    const float* x  = (const float*)d_in[0];
    const float* w1 = (const float*)d_in[2];
    const float* b1 = (const float*)d_in[3];
    const float* w2 = (const float*)d_in[4];
    const float* b2 = (const float*)d_in[5];

    void *xh, *w1h, *w2h, *sh;
    cudaGetSymbolAddress(&xh,  g_Xh);
    cudaGetSymbolAddress(&w1h, g_W1h);
    cudaGetSymbolAddress(&w2h, g_W2h);
    cudaGetSymbolAddress(&sh,  g_Sh);

    // convert X + W1 in a single launch (GEMM1 inputs)
    // units of 8 elements: X 5,898,240 + W1 16,588,800 = 22,487,040 units
    {
        long long nxu   = (long long)T_TOK * DDIM / 8;
        long long nw1u  = (long long)NEXP * N1 * KDIM / 8;
        long long ntotu = nxu + nw1u;
        unsigned nblk = (unsigned)((ntotu + 2LL * 256 - 1) / (2LL * 256));
        cvt_xw1<<<nblk, 256>>>(
            (const float4*)x,  (uint4*)xh,  nxu,
            (const float4*)w1, (uint4*)w1h, ntotu);
    }

    cudaFuncSetAttribute(gemm_f16<0>, cudaFuncAttributeMaxDynamicSharedMemorySize, SMEM_BYTES);
    cudaFuncSetAttribute(gemm_f16<1>, cudaFuncAttributeMaxDynamicSharedMemorySize, SMEM_BYTES);

    // GEMM1 + swiglu (z 0..7) and W2 conversion tail blocks (z 8..15),
    // one launch: cvt blocks backfill GEMM1's drain waves.
    gemm_f16<0><<<dim3(G1X, G1Y, NEXP + ZEXTRA), NTHREADS, SMEM_BYTES>>>(
        (const __half*)xh, (const __half*)w1h, b1, sh, N1,
        (const float4*)w2, (uint4*)w2h);

    // GEMM2 + bias: N = 2880 -> 18 tiles of 160 (exact)
    gemm_f16<1><<<dim3(DDIM / BN, CEXP / BM, NEXP), NTHREADS, SMEM_BYTES>>>(
        (const __half*)sh, (const __half*)w2h, b2, d_out, DDIM,
        nullptr, nullptr);
}

// round 16
// speedup vs baseline: 1.0340x; 1.0340x over previous
#include <cuda_runtime.h>
#include <cuda_fp16.h>
#include <cstdint>
#include <cstddef>

// ---------------- problem constants ----------------
static constexpr int T_TOK = 16384;
static constexpr int DDIM  = 2880;
static constexpr int HDIM  = 2880;
static constexpr int NEXP  = 8;
static constexpr int CEXP  = T_TOK / NEXP;   // 2048 tokens per expert
static constexpr int N1    = 2 * HDIM;       // 5760
static constexpr int KDIM  = 2880;

// ---------------- tile config (2 CTAs / SM) ----------------
static constexpr int BM = 128;
static constexpr int BN = 160;               // 5760/160=36, 2880/160=18 (both exact)
static constexpr int BK = 64;                // 128 bytes of fp16 per row-slice
static constexpr int KI = KDIM / BK;         // 45
static constexpr int NSTAGE = 3;
static constexpr int NTHREADS = 128;         // 4 warps: 2(m) x 2(n)

static constexpr int WM = 64;                // warp tile M
static constexpr int WN = 80;                // warp tile N

static constexpr int A_STAGE = BM * 128;     // 16384 B
static constexpr int B_STAGE = BN * 128;     // 20480 B
static constexpr int A_OFF    = 0;
static constexpr int B_OFF    = NSTAGE * A_STAGE;             // 49152
static constexpr int BIAS_OFF = B_OFF + NSTAGE * B_STAGE;     // 110592
static constexpr int SMEM_USE  = BIAS_OFF + BN * 4;           // 111232
static constexpr int SMEM_BYTES = SMEM_USE + 256;             // 111488 (x2 = 222.9K/SM)

// ---- fused W2-conversion tail blocks (ride along with GEMM1's launch) ----
// R14-proven shape: 1 float4 (16B fp32) -> 1 uint2 (8B fp16) per element op
static constexpr long long NW2_4      = (long long)NEXP * DDIM * HDIM / 4;  // 16,588,800 float4
static constexpr int       CVT_CHUNK  = 4096;                               // float4 per cvt block
static constexpr int       NCVT_BLK   = (int)(NW2_4 / CVT_CHUNK);           // 4050 (exact)
static constexpr int       G1X = N1 / BN;      // 36
static constexpr int       G1Y = CEXP / BM;    // 16
static constexpr int       ZEXTRA = (NCVT_BLK + G1X * G1Y - 1) / (G1X * G1Y); // 8

// ---------------- scratch (static device arrays: no allocation) -----------
__device__ __half g_Xh [(size_t)T_TOK * DDIM];
__device__ __half g_W1h[(size_t)NEXP * N1 * KDIM];
__device__ __half g_W2h[(size_t)NEXP * DDIM * HDIM];
__device__ __half g_Sh [(size_t)T_TOK * HDIM];

// ---------------- PTX helpers ----------------
__device__ __forceinline__ uint32_t smem_u32(const void* p) {
    uint32_t a;
    asm("{ .reg .u64 t; cvta.to.shared.u64 t, %1; cvt.u32.u64 %0, t; }"
        : "=r"(a) : "l"(p));
    return a;
}

__device__ __forceinline__ uint32_t swz128(uint32_t off) {
    return off ^ ((off >> 3) & 0x70);
}

__device__ __forceinline__ void cp16(uint32_t dst, const void* src) {
    asm volatile("cp.async.cg.shared.global [%0], [%1], 16;"
                 :: "r"(dst), "l"(src) : "memory");
}
__device__ __forceinline__ void cp_commit() {
    asm volatile("cp.async.commit_group;" ::: "memory");
}
__device__ __forceinline__ void cp_wait1() {
    asm volatile("cp.async.wait_group 1;" ::: "memory");
}

__device__ __forceinline__ void ldsm_x4(uint32_t* d, uint32_t addr) {
    asm volatile("ldmatrix.sync.aligned.m8n8.x4.shared.b16 {%0,%1,%2,%3}, [%4];"
                 : "=r"(d[0]), "=r"(d[1]), "=r"(d[2]), "=r"(d[3]) : "r"(addr));
}

__device__ __forceinline__ void mma16816(float* c, const uint32_t* a,
                                         uint32_t b0, uint32_t b1) {
    asm volatile("mma.sync.aligned.m16n8k16.row.col.f32.f16.f16.f32 "
                 "{%0,%1,%2,%3}, {%4,%5,%6,%7}, {%8,%9}, {%0,%1,%2,%3};"
                 : "+f"(c[0]), "+f"(c[1]), "+f"(c[2]), "+f"(c[3])
                 : "r"(a[0]), "r"(a[1]), "r"(a[2]), "r"(a[3]),
                   "r"(b0), "r"(b1));
}

__device__ __forceinline__ uint2 cvt4(const float4& v) {
    __half2 h0 = __floats2half2_rn(v.x, v.y);
    __half2 h1 = __floats2half2_rn(v.z, v.w);
    uint2 o;
    o.x = *reinterpret_cast<const uint32_t*>(&h0);
    o.y = *reinterpret_cast<const uint32_t*>(&h1);
    return o;
}

// 2x float4 -> uint4 (8 fp32 -> 8 fp16); streaming loads, NORMAL stores
// (converted data should stay L2-resident for GEMM1's first waves)
__device__ __forceinline__ uint4 cvt8(const float4* __restrict__ p) {
    float4 a = __ldcs(p);
    float4 b = __ldcs(p + 1);
    __half2 h0 = __floats2half2_rn(a.x, a.y);
    __half2 h1 = __floats2half2_rn(a.z, a.w);
    __half2 h2 = __floats2half2_rn(b.x, b.y);
    __half2 h3 = __floats2half2_rn(b.z, b.w);
    uint4 o;
    o.x = *reinterpret_cast<const uint32_t*>(&h0);
    o.y = *reinterpret_cast<const uint32_t*>(&h1);
    o.z = *reinterpret_cast<const uint32_t*>(&h2);
    o.w = *reinterpret_cast<const uint32_t*>(&h3);
    return o;
}

// ---------------- fp32 -> fp16 convert: X and W1 in one launch ----------------
// unit i: converts elements [8i, 8i+8). X units first, then W1 units.
__global__ void cvt_xw1(const float4* __restrict__ xs, uint4* __restrict__ xd,
                        long long nxu,
                        const float4* __restrict__ ws, uint4* __restrict__ wd,
                        long long ntotu) {
    const long long stride = (long long)gridDim.x * blockDim.x;
    long long i = (long long)blockIdx.x * blockDim.x + threadIdx.x;
    #pragma unroll
    for (int r = 0; r < 2; ++r, i += stride) {
        if (i < nxu) {
            xd[i] = cvt8(xs + 2 * i);
        } else if (i < ntotu) {
            long long j = i - nxu;
            wd[j] = cvt8(ws + 2 * j);
        }
    }
}

// ---------------- fused GEMM (+swiglu on EPI==0) ----------------
// D[m, n] = sum_k A[m, k] * B[n, k]  (both K-major fp16)
// EPI==0: out = __half S after swiglu on (even, odd) col pairs; grid.z > NEXP
//         blocks are W2 fp32->fp16 convert blocks (tail-filled behind GEMM)
// EPI==1: out = float + bias
template <int EPI>
__global__ void __launch_bounds__(NTHREADS, 2)
gemm_f16(const __half* __restrict__ A,
         const __half* __restrict__ B,
         const float* __restrict__ bias,
         void* __restrict__ outp,
         int Ntot,
         const float4* __restrict__ cvt_src,
         uint2* __restrict__ cvt_dst) {
    const int tid = threadIdx.x;

    if (EPI == 0 && blockIdx.z >= (unsigned)NEXP) {
        // -------- W2 conversion tail block (exact R14 shape) --------
        int cid = (int)blockIdx.x +
                  (int)gridDim.x * ((int)blockIdx.y +
                  (int)gridDim.y * ((int)blockIdx.z - NEXP));
        if (cid < NCVT_BLK) {
            long long base = (long long)cid * CVT_CHUNK + tid;
            #pragma unroll
            for (int j = 0; j < CVT_CHUNK / NTHREADS; ++j) {
                long long idx = base + (long long)j * NTHREADS;
                cvt_dst[idx] = cvt4(cvt_src[idx]);
            }
        }
        return;
    }

    extern __shared__ char smem_raw[];
    const uint32_t sbase = smem_u32(smem_raw);

    const int lane = tid & 31;
    const int wid  = tid >> 5;               // 0..3
    const int wm   = (wid & 1) * WM;         // warp M offset (2 warps in M)
    const int wn   = (wid >> 1) * WN;        // warp N offset (2 warps in N)

    const int bn  = blockIdx.x;
    const int bm  = blockIdx.y;
    const int e   = blockIdx.z;
    const int n0  = bn * BN;
    const size_t row0 = (size_t)e * CEXP + (size_t)bm * BM;

    const __half* Aexp = A + row0 * KDIM;
    const __half* Bexp = B + ((size_t)e * Ntot + n0) * KDIM;

    // bias tile -> smem
    for (int i = tid; i < BN; i += NTHREADS) {
        float v = bias[(size_t)e * Ntot + n0 + i];
        asm volatile("st.shared.f32 [%0], %1;"
                     :: "r"(sbase + BIAS_OFF + i * 4), "f"(v) : "memory");
    }

    // ---- stage loader (A: 1024 chunks -> 8/thread, B: 1280 -> 10/thread) ----
    auto load_stage = [&](int s_, int kt) {
        const int koff = kt * BK;
        const uint32_t abase = sbase + A_OFF + s_ * A_STAGE;
        const uint32_t bbase = sbase + B_OFF + s_ * B_STAGE;
        #pragma unroll
        for (int j = 0; j < 8; ++j) {
            int c = tid + j * NTHREADS;
            int r = c >> 3, q = c & 7;
            cp16(abase + swz128((uint32_t)(r * 128 + q * 16)),
                 Aexp + (size_t)r * KDIM + koff + q * 8);
        }
        #pragma unroll
        for (int j = 0; j < 10; ++j) {
            int c = tid + j * NTHREADS;
            int r = c >> 3, q = c & 7;
            cp16(bbase + swz128((uint32_t)(r * 128 + q * 16)),
                 Bexp + (size_t)r * KDIM + koff + q * 8);
        }
    };

    // prologue: fill stages 0,1 (one commit group each)
    load_stage(0, 0); cp_commit();
    load_stage(1, 1); cp_commit();

    // accumulators: 4 m-frags x 10 n8-frags x 4 floats = 160 regs
    float acc[4][10][4];
    #pragma unroll
    for (int i = 0; i < 4; ++i)
        #pragma unroll
        for (int j = 0; j < 10; ++j)
            #pragma unroll
            for (int q = 0; q < 4; ++q) acc[i][j][q] = 0.0f;

    // per-lane ldmatrix row/col selectors (stage-invariant parts)
    const int a_row  = wm + (lane & 15);        // + mf*16
    const int a_k8   = (lane >> 4) * 16;        // byte offset within 32B k-step
    const int b_row  = wn + ((lane & 15) & 7) + 8 * (lane >> 4);  // + nf*16
    const int b_k8   = (((lane & 15) >> 3)) * 16;

    int s  = 0;       // compute stage
    int sj = 2;       // load stage
    for (int it = 0; it < KI; ++it) {
        // one commit group per iteration (possibly empty) keeps wait_group exact
        cp_wait1();
        __syncthreads();

        const int jn = it + 2;
        if (jn < KI) load_stage(sj, jn);
        cp_commit();

        const uint32_t sA = sbase + A_OFF + s * A_STAGE;
        const uint32_t sB = sbase + B_OFF + s * B_STAGE;

        #pragma unroll
        for (int ks = 0; ks < 4; ++ks) {
            const int kb = ks * 32;
            uint32_t a[4][4];
            #pragma unroll
            for (int mf = 0; mf < 4; ++mf)
                ldsm_x4(a[mf], sA + swz128((uint32_t)((a_row + mf * 16) * 128 + kb + a_k8)));
            #pragma unroll
            for (int nf = 0; nf < 5; ++nf) {
                uint32_t b[4];
                ldsm_x4(b, sB + swz128((uint32_t)((b_row + nf * 16) * 128 + kb + b_k8)));
                #pragma unroll
                for (int mf = 0; mf < 4; ++mf) {
                    mma16816(acc[mf][2 * nf],     a[mf], b[0], b[1]);
                    mma16816(acc[mf][2 * nf + 1], a[mf], b[2], b[3]);
                }
            }
        }
        s  = (s  == NSTAGE - 1) ? 0 : s + 1;
        sj = (sj == NSTAGE - 1) ? 0 : sj + 1;
    }
    __syncthreads();

    // ---------------- epilogue ----------------
    const int grp = lane >> 2;        // row within m16 frag
    const int tq  = lane & 3;         // col pair selector

    #pragma unroll
    for (int mf = 0; mf < 4; ++mf) {
        const size_t r0g = row0 + wm + mf * 16 + grp;
        const size_t r1g = r0g + 8;
        #pragma unroll
        for (int nf = 0; nf < 10; ++nf) {
            const int ncol = wn + nf * 8 + 2 * tq;     // even col in tile
            float bg, bl;
            asm volatile("ld.shared.f32 %0, [%1];" : "=f"(bg)
                         : "r"(sbase + BIAS_OFF + ncol * 4));
            asm volatile("ld.shared.f32 %0, [%1];" : "=f"(bl)
                         : "r"(sbase + BIAS_OFF + (ncol + 1) * 4));
            if (EPI == 0) {
                // swiglu: g = even col, l = odd col
                #pragma unroll
                for (int half_ : {0, 1}) {
                    float g = acc[mf][nf][2 * half_]     + bg;
                    float l = acc[mf][nf][2 * half_ + 1] + bl;
                    g = fminf(g, 7.0f);
                    l = fminf(fmaxf(l, -7.0f), 7.0f);
                    float sig = 1.0f / (1.0f + __expf(-1.702f * g));
                    float sv  = g * sig * (l + 1.0f);
                    size_t row = half_ ? r1g : r0g;
                    ((__half*)outp)[row * (size_t)HDIM + ((n0 + ncol) >> 1)] = __float2half_rn(sv);
                }
            } else {
                float2 v0 = make_float2(acc[mf][nf][0] + bg, acc[mf][nf][1] + bl);
                float2 v1 = make_float2(acc[mf][nf][2] + bg, acc[mf][nf][3] + bl);
                float* oo = (float*)outp;
                *reinterpret_cast<float2*>(oo + r0g * (size_t)DDIM + n0 + ncol) = v0;
                *reinterpret_cast<float2*>(oo + r1g * (size_t)DDIM + n0 + ncol) = v1;
            }
        }
    }
}

// ---------------- launch ----------------
extern "C" void kernel_launch(void* const* d_in, const int* in_sizes, int n_in,
                              void* d_out, int out_size) {
    const float* x  = (const float*)d_in[0];
    const float* w1 = (const float*)d_in[2];
    const float* b1 = (const float*)d_in[3];
    const float* w2 = (const float*)d_in[4];
    const float* b2 = (const float*)d_in[5];

    void *xh, *w1h, *w2h, *sh;
    cudaGetSymbolAddress(&xh,  g_Xh);
    cudaGetSymbolAddress(&w1h, g_W1h);
    cudaGetSymbolAddress(&w2h, g_W2h);
    cudaGetSymbolAddress(&sh,  g_Sh);

    // convert X + W1 in a single launch (GEMM1 inputs)
    // units of 8 elements: X 5,898,240 + W1 16,588,800 = 22,487,040 units
    {
        long long nxu   = (long long)T_TOK * DDIM / 8;
        long long nw1u  = (long long)NEXP * N1 * KDIM / 8;
        long long ntotu = nxu + nw1u;
        unsigned nblk = (unsigned)((ntotu + 2LL * 256 - 1) / (2LL * 256));
        cvt_xw1<<<nblk, 256>>>(
            (const float4*)x,  (uint4*)xh,  nxu,
            (const float4*)w1, (uint4*)w1h, ntotu);
    }

    cudaFuncSetAttribute(gemm_f16<0>, cudaFuncAttributeMaxDynamicSharedMemorySize, SMEM_BYTES);
    cudaFuncSetAttribute(gemm_f16<1>, cudaFuncAttributeMaxDynamicSharedMemorySize, SMEM_BYTES);

    // GEMM1 + swiglu (z 0..7) and W2 conversion tail blocks (z 8..15),
    // one launch: cvt blocks backfill GEMM1's drain waves.
    gemm_f16<0><<<dim3(G1X, G1Y, NEXP + ZEXTRA), NTHREADS, SMEM_BYTES>>>(
        (const __half*)xh, (const __half*)w1h, b1, sh, N1,
        (const float4*)w2, (uint2*)w2h);

    // GEMM2 + bias: N = 2880 -> 18 tiles of 160 (exact)
    gemm_f16<1><<<dim3(DDIM / BN, CEXP / BM, NEXP), NTHREADS, SMEM_BYTES>>>(
        (const __half*)sh, (const __half*)w2h, b2, d_out, DDIM,
        nullptr, nullptr);
}